// round 15
// baseline (speedup 1.0000x reference)
#include <cuda_runtime.h>
#include <cuda_bf16.h>
#include <cuda_fp16.h>
#include <cstdint>
#include <cmath>

#define Bsz 32
#define Tlen 128
#define Dd 192
#define H4d 768
#define Ll 6
#define Vv 32000
#define BT (Bsz*Tlen)            // 4096
#define BTV ((size_t)BT*(size_t)Vv)
#define KEXT 576                 // bf16 3-way split K (gx GEMMs)
#define KHEAD 192                // plain fp16 head GEMM K

typedef unsigned long long ull;

// ---------------- scratch ----------------
__device__ __align__(128) float g_h[BT*Dd];
__device__ __align__(128) float g_gx[BT*H4d];
__device__ __align__(128) __nv_bfloat16 g_Aext[BT*KEXT];              // [hi|hi|lo]
__device__ __align__(128) __nv_bfloat16 g_Wext[(size_t)Ll*H4d*KEXT];  // [hi|lo|hi]
__device__ __align__(128) __half g_Ahead[(size_t)BT*KHEAD];           // fp16(LN(h))
__device__ __align__(128) __half g_Bh[(size_t)Vv*Dd];                 // fp16(tok)

// ---------------- helpers ----------------
__device__ __forceinline__ uint32_t smem_u32(const void* p){
    uint32_t a;
    asm("{ .reg .u64 t; cvta.to.shared.u64 t, %1; cvt.u32.u64 %0, t; }"
        : "=r"(a) : "l"(p));
    return a;
}
__device__ __forceinline__ float2 unpack2(ull v){
    unsigned int lo, hi;
    asm("mov.b64 {%0, %1}, %2;" : "=r"(lo), "=r"(hi) : "l"(v));
    return make_float2(__uint_as_float(lo), __uint_as_float(hi));
}
__device__ __forceinline__ void fma2(ull &d, ull a, ull b){
    asm("fma.rn.f32x2 %0, %1, %2, %3;" : "=l"(d) : "l"(a), "l"(b), "l"(d));
}
__device__ __forceinline__ void cp16(uint32_t s, const void* g){
    asm volatile("cp.async.cg.shared.global [%0], [%1], 16;" :: "r"(s), "l"(g) : "memory");
}
#define SW128(x) ((x) ^ (((x) >> 3) & 0x70))

__device__ __forceinline__ void ldm4(uint32_t &r0, uint32_t &r1,
                                     uint32_t &r2, uint32_t &r3, uint32_t a){
    asm volatile("ldmatrix.sync.aligned.m8n8.x4.shared.b16 {%0,%1,%2,%3}, [%4];"
        : "=r"(r0), "=r"(r1), "=r"(r2), "=r"(r3) : "r"(a));
}
template<bool HALF>
__device__ __forceinline__ void mma16816(float* d, const uint32_t* a,
                                         uint32_t b0, uint32_t b1){
    if (HALF)
        asm volatile("mma.sync.aligned.m16n8k16.row.col.f32.f16.f16.f32 "
            "{%0,%1,%2,%3}, {%4,%5,%6,%7}, {%8,%9}, {%0,%1,%2,%3};"
            : "+f"(d[0]), "+f"(d[1]), "+f"(d[2]), "+f"(d[3])
            : "r"(a[0]), "r"(a[1]), "r"(a[2]), "r"(a[3]), "r"(b0), "r"(b1));
    else
        asm volatile("mma.sync.aligned.m16n8k16.row.col.f32.bf16.bf16.f32 "
            "{%0,%1,%2,%3}, {%4,%5,%6,%7}, {%8,%9}, {%0,%1,%2,%3};"
            : "+f"(d[0]), "+f"(d[1]), "+f"(d[2]), "+f"(d[3])
            : "r"(a[0]), "r"(a[1]), "r"(a[2]), "r"(a[3]), "r"(b0), "r"(b1));
}

__device__ __forceinline__ float fast_sig(float x){
    float e, r;
    asm("ex2.approx.f32 %0, %1;" : "=f"(e) : "f"(x * -1.4426950408889634f));
    asm("rcp.approx.f32 %0, %1;" : "=f"(r) : "f"(e + 1.0f));
    return r;
}
__device__ __forceinline__ float fast_tanh(float x){
    float e, r;
    asm("ex2.approx.f32 %0, %1;" : "=f"(e) : "f"(x * -2.8853900817779268f));
    asm("rcp.approx.f32 %0, %1;" : "=f"(r) : "f"(e + 1.0f));
    return fmaf(2.f, r, -1.f);
}

// ---------------- embedding + bf16 3-way split [hi|hi|lo] ----------------
__global__ void embed_split(const int* __restrict__ x,
                            const float* __restrict__ tok,
                            const float* __restrict__ pos){
    int row = blockIdx.x;
    int t   = row & (Tlen - 1);
    int c   = threadIdx.x;
    int v   = x[row];
    float a = tok[(size_t)v*Dd + c] + pos[t*Dd + c];
    __nv_bfloat16 hi = __float2bfloat16(a);
    __nv_bfloat16 lo = __float2bfloat16(a - __bfloat162float(hi));
    size_t b = (size_t)row*KEXT;
    g_Aext[b + c] = hi; g_Aext[b + Dd + c] = hi; g_Aext[b + 2*Dd + c] = lo;
}

// ---------------- fused weight conversion (tok->fp16, W_ih->bf16 3-way) ---------
__global__ void conv_all(const float* __restrict__ tok,
                         const float* __restrict__ W_ih){
    int row = blockIdx.x, c = threadIdx.x;
    if (row < Vv){
        g_Bh[(size_t)row*Dd + c] = __float2half_rn(tok[(size_t)row*Dd + c]);
    } else {
        int r2 = row - Vv;
        float a = W_ih[(size_t)r2*Dd + c];
        __nv_bfloat16 hi = __float2bfloat16(a);
        __nv_bfloat16 lo = __float2bfloat16(a - __bfloat162float(hi));
        size_t b = (size_t)r2*KEXT;
        g_Wext[b + c] = hi; g_Wext[b + Dd + c] = lo; g_Wext[b + 2*Dd + c] = hi;
    }
}

// ---------------- gx GEMM (bf16 3-way, K=576): CTA 64x128, 4 warps, 3 CTA/SM ----
#define GXSTAGE 24576
#define GX_SMEM (3*GXSTAGE + 1024)

template<int KCH, bool BIAS>
__global__ __launch_bounds__(128,3) void mma_gemm(
    const void* __restrict__ A, const void* __restrict__ Bw,
    const float* __restrict__ b1, const float* __restrict__ b2,
    float* __restrict__ C, int N)
{
    extern __shared__ char smem_raw[];
    const uint32_t sbase = (smem_u32(smem_raw) + 1023u) & ~1023u;
    const int KA = KCH*64;

    const int t    = threadIdx.x;
    const int lane = t & 31;
    const int wid  = t >> 5;
    const int m0   = blockIdx.y * 64;
    const int n0   = blockIdx.x * 128;
    const int mw   = (wid & 1) * 32;
    const int nw   = (wid >> 1) * 64;

    const char* Ab = (const char*)A;
    const char* Bb = (const char*)Bw;
    uint32_t sAoff[4], gAoff[4];
    #pragma unroll
    for (int i=0;i<4;i++){
        int idx = t + i*128, row = idx>>3, cc = idx&7;
        sAoff[i] = SW128((uint32_t)(row*128 + cc*16));
        gAoff[i] = (uint32_t)((m0+row)*KA*2 + cc*16);
    }
    uint32_t sBoff[8], gBoff[8];
    #pragma unroll
    for (int i=0;i<8;i++){
        int idx = t + i*128, row = idx>>3, cc = idx&7;
        sBoff[i] = 8192u + SW128((uint32_t)(row*128 + cc*16));
        gBoff[i] = (uint32_t)((n0+row)*KA*2 + cc*16);
    }

    uint32_t aOff[2], bOff[4];
    {
        int r = lane & 15, hc = (lane >> 4) * 16;
        #pragma unroll
        for (int mt=0; mt<2; mt++)
            aOff[mt] = SW128((uint32_t)((mw + mt*16 + r)*128 + hc));
        #pragma unroll
        for (int p=0; p<4; p++)
            bOff[p] = 8192u + SW128((uint32_t)((nw + p*16 + r)*128 + hc));
    }

    float acc[2][8][4];
    #pragma unroll
    for (int i=0;i<2;i++)
        #pragma unroll
        for (int j=0;j<8;j++)
            #pragma unroll
            for (int k=0;k<4;k++) acc[i][j][k] = 0.f;

    #pragma unroll
    for (int s=0;s<2;s++){
        uint32_t sb = sbase + s*GXSTAGE;
        uint32_t ka = (uint32_t)s*128;
        #pragma unroll
        for (int i=0;i<4;i++) cp16(sb + sAoff[i], Ab + gAoff[i] + ka);
        #pragma unroll
        for (int i=0;i<8;i++) cp16(sb + sBoff[i], Bb + gBoff[i] + ka);
        asm volatile("cp.async.commit_group;" ::: "memory");
    }

    int sidx = 0;
    #pragma unroll 1
    for (int k0 = 0; k0 < KCH; k0++){
        if (k0 == KCH-1) asm volatile("cp.async.wait_group 0;" ::: "memory");
        else             asm volatile("cp.async.wait_group 1;" ::: "memory");
        __syncthreads();

        if (k0 + 2 < KCH){
            int s2 = sidx + 2; if (s2 >= 3) s2 -= 3;
            uint32_t sb = sbase + s2*GXSTAGE;
            uint32_t ka = (uint32_t)(k0+2)*128;
            #pragma unroll
            for (int i=0;i<4;i++) cp16(sb + sAoff[i], Ab + gAoff[i] + ka);
            #pragma unroll
            for (int i=0;i<8;i++) cp16(sb + sBoff[i], Bb + gBoff[i] + ka);
            asm volatile("cp.async.commit_group;" ::: "memory");
        }

        const uint32_t sb = sbase + sidx*GXSTAGE;
        #pragma unroll
        for (int ks=0; ks<4; ks++){
            const uint32_t kx = ks*32;
            uint32_t a[2][4];
            ldm4(a[0][0], a[0][1], a[0][2], a[0][3], sb + (aOff[0]^kx));
            ldm4(a[1][0], a[1][1], a[1][2], a[1][3], sb + (aOff[1]^kx));
            #pragma unroll
            for (int p=0; p<4; p++){
                uint32_t r0,r1,r2,r3;
                ldm4(r0, r1, r2, r3, sb + (bOff[p]^kx));
                mma16816<false>(acc[0][2*p],   a[0], r0, r2);
                mma16816<false>(acc[0][2*p+1], a[0], r1, r3);
                mma16816<false>(acc[1][2*p],   a[1], r0, r2);
                mma16816<false>(acc[1][2*p+1], a[1], r1, r3);
            }
        }
        sidx++; if (sidx == 3) sidx = 0;
    }

    const int g  = lane >> 2;
    const int tc = (lane & 3) * 2;
    #pragma unroll
    for (int mt=0; mt<2; mt++){
        const int row = m0 + mw + mt*16 + g;
        #pragma unroll
        for (int nt=0; nt<8; nt++){
            const int col = n0 + nw + (nt>>1)*16 + (nt&1)*8 + tc;
            float bb0 = 0.f, bb1 = 0.f;
            if (BIAS){ bb0 = b1[col] + b2[col]; bb1 = b1[col+1] + b2[col+1]; }
            float2 v0 = make_float2(acc[mt][nt][0] + bb0, acc[mt][nt][1] + bb1);
            float2 v1 = make_float2(acc[mt][nt][2] + bb0, acc[mt][nt][3] + bb1);
            *reinterpret_cast<float2*>(C + (size_t)row*N + col)     = v0;
            *reinterpret_cast<float2*>(C + (size_t)(row+8)*N + col) = v1;
        }
    }
}

// ---------------- head GEMM: fp16 K=192, A+B fully smem-resident (r9) -----------
#define HEAD_SMEM (98304 + 1024)

__global__ __launch_bounds__(128,2) void head_gemm(
    const __half* __restrict__ A, const __half* __restrict__ Bw,
    float* __restrict__ C, int N)
{
    extern __shared__ char smem_raw[];
    const uint32_t sbase = (smem_u32(smem_raw) + 1023u) & ~1023u;
    const uint32_t sA = sbase;
    const uint32_t sB = sbase + 49152;

    const int t    = threadIdx.x;
    const int lane = t & 31;
    const int wid  = t >> 5;
    const int m0   = blockIdx.y * 128;
    const int n0   = blockIdx.x * 128;
    const int wm   = (wid & 1) * 64;
    const int wn   = (wid >> 1) * 64;

    #pragma unroll
    for (int i=0;i<24;i++){
        int idx = t + i*128;
        int c = idx>>10, rem = idx&1023, row = rem>>3, cc = rem&7;
        uint32_t sw = SW128((uint32_t)(row*128 + cc*16));
        cp16(sA + c*16384 + sw,
             (const char*)A  + (size_t)(m0+row)*(KHEAD*2) + c*128 + cc*16);
        cp16(sB + c*16384 + sw,
             (const char*)Bw + (size_t)(n0+row)*(Dd*2)    + c*128 + cc*16);
    }
    asm volatile("cp.async.commit_group;" ::: "memory");

    uint32_t aOff[4], bOff[4];
    {
        int r = lane & 15, hc = (lane >> 4) * 16;
        #pragma unroll
        for (int mt=0; mt<4; mt++)
            aOff[mt] = SW128((uint32_t)((wm + mt*16 + r)*128 + hc));
        #pragma unroll
        for (int p=0; p<4; p++)
            bOff[p] = SW128((uint32_t)((wn + p*16 + r)*128 + hc));
    }

    float acc[4][8][4];
    #pragma unroll
    for (int i=0;i<4;i++)
        #pragma unroll
        for (int j=0;j<8;j++)
            #pragma unroll
            for (int k=0;k<4;k++) acc[i][j][k] = 0.f;

    asm volatile("cp.async.wait_group 0;" ::: "memory");
    __syncthreads();

    #pragma unroll
    for (int k0 = 0; k0 < 3; k0++){
        const uint32_t sbA = sA + k0*16384;
        const uint32_t sbB = sB + k0*16384;
        #pragma unroll
        for (int ks=0; ks<4; ks++){
            const uint32_t kx = ks*32;
            uint32_t a[4][4], b[4][4];
            #pragma unroll
            for (int mt=0; mt<4; mt++)
                ldm4(a[mt][0], a[mt][1], a[mt][2], a[mt][3], sbA + (aOff[mt]^kx));
            #pragma unroll
            for (int p=0; p<4; p++)
                ldm4(b[p][0], b[p][1], b[p][2], b[p][3], sbB + (bOff[p]^kx));
            #pragma unroll
            for (int p=0; p<4; p++)
                #pragma unroll
                for (int mt=0; mt<4; mt++){
                    mma16816<true>(acc[mt][2*p],   a[mt], b[p][0], b[p][2]);
                    mma16816<true>(acc[mt][2*p+1], a[mt], b[p][1], b[p][3]);
                }
        }
    }

    const int g  = lane >> 2;
    const int tc = (lane & 3) * 2;
    #pragma unroll
    for (int mt=0; mt<4; mt++){
        const int row = m0 + wm + mt*16 + g;
        #pragma unroll
        for (int nt=0; nt<8; nt++){
            const int col = n0 + wn + (nt>>1)*16 + (nt&1)*8 + tc;
            float2 v0 = make_float2(acc[mt][nt][0], acc[mt][nt][1]);
            float2 v1 = make_float2(acc[mt][nt][2], acc[mt][nt][3]);
            *reinterpret_cast<float2*>(C + (size_t)row*N + col)     = v0;
            *reinterpret_cast<float2*>(C + (size_t)(row+8)*N + col) = v1;
        }
    }
}

// ---------------- LSTM: r12 step body + release-flag cluster sync ---------------
// Replaces barrier.cluster with: producers release-store per-thread flags (t+1)
// into flags[unit][rank] of every CTA; threads 0-47 acquire-poll their 4 local
// flags; __syncthreads releases the CTA. No fences, no atomics.
__global__ __launch_bounds__(384,1) __cluster_dims__(4,1,1)
void lstm_kernel(const float* __restrict__ Wl)
{
    __shared__ float h_buf[2][Dd];
    __shared__ float partial[Dd];
    __shared__ float gsm[Dd];
    __shared__ __align__(16) unsigned int flags[48*4];   // flags[unit*4 + rank]

    const int r   = blockIdx.x;
    const int b   = blockIdx.y;
    const int tid = threadIdx.x;
    const int half = (tid >= Dd) ? 1 : 0;
    const int j    = tid - half*Dd;
    const int q    = j / 48;
    const int u    = j - q*48;
    const int row_g = q*Dd + r*48 + u;

    ull w2[48];
    const ull* wp = (const ull*)(Wl + (size_t)row_g*Dd + half*96);
    #pragma unroll
    for (int k=0;k<48;k++) w2[k] = wp[k];

    for (int i = tid; i < 2*Dd; i += 384) (&h_buf[0][0])[i] = 0.f;
    if (tid < 192) flags[tid] = 0;
    asm volatile("barrier.cluster.arrive.aligned;\n\t"
                 "barrier.cluster.wait.aligned;" ::: "memory");

    const float* gx_base = g_gx + (size_t)b*Tlen*H4d + row_g;
    float*       h_out   = g_h  + (size_t)b*Tlen*Dd;
    const uint32_t hb = smem_u32(&h_buf[0][0]);
    const uint32_t fb = smem_u32(&flags[0]);

    const int u2 = tid >> 2;
    const int g2 = tid & 3;
    uint32_t ra[2][4], rf[4];
    if (tid < Dd && g2 == 0){
        uint32_t la0 = hb + (uint32_t)(r*48 + u2)*4u;
        uint32_t lf  = fb + (uint32_t)(u2*4 + r)*4u;
        #pragma unroll
        for (int rk=0; rk<4; rk++){
            asm("mapa.shared::cluster.u32 %0, %1, %2;" : "=r"(ra[0][rk]) : "r"(la0),        "r"(rk));
            asm("mapa.shared::cluster.u32 %0, %1, %2;" : "=r"(ra[1][rk]) : "r"(la0 + 768u), "r"(rk));
            asm("mapa.shared::cluster.u32 %0, %1, %2;" : "=r"(rf[rk])    : "r"(lf),          "r"(rk));
        }
    }
    const uint32_t pf = fb + (uint32_t)tid*16u;   // poll base for tid<48

    float c = 0.f;
    float gxv = (!half) ? gx_base[0] : 0.f;

    int cur = 0;
    #pragma unroll 1
    for (int t = 0; t < Tlen; t++){
        const ull* hp = (const ull*)(&h_buf[cur][half*96]);
        ull a0=0ULL, a1=0ULL, a2=0ULL, a3=0ULL;
        #pragma unroll
        for (int k=0;k<48;k+=4){
            fma2(a0, w2[k+0], hp[k+0]);
            fma2(a1, w2[k+1], hp[k+1]);
            fma2(a2, w2[k+2], hp[k+2]);
            fma2(a3, w2[k+3], hp[k+3]);
        }
        float2 f0=unpack2(a0), f1=unpack2(a1), f2=unpack2(a2), f3=unpack2(a3);
        float acc = ((f0.x+f0.y)+(f1.x+f1.y)) + ((f2.x+f2.y)+(f3.x+f3.y));

        if (half) partial[j] = acc;
        __syncthreads();
        if (!half) gsm[j] = acc + partial[j] + gxv;
        __syncthreads();
        if (!half){
            int tn = (t+1 < Tlen) ? t+1 : t;
            gxv = gx_base[(size_t)tn*H4d];
        }

        const int nxt = cur ^ 1;
        float hn = 0.f;
        if (tid < Dd){
            float val = gsm[g2*48 + u2];
            float nl  = (g2 == 2) ? fast_tanh(val) : fast_sig(val);
            const int lb = (tid & 31) & ~3;
            float fi  = __shfl_sync(0xffffffffu, nl, lb);
            float ff  = __shfl_sync(0xffffffffu, nl, lb|1);
            float fgg = __shfl_sync(0xffffffffu, nl, lb|2);
            float fo  = __shfl_sync(0xffffffffu, nl, lb|3);
            if (g2 == 0){
                c = ff*c + fi*fgg;
                hn = fo * fast_tanh(c);
                #pragma unroll
                for (int rk=0; rk<4; rk++)
                    asm volatile("st.shared::cluster.f32 [%0], %1;"
                                 :: "r"(ra[nxt][rk]), "f"(hn) : "memory");
                // release flags: order own h stores before flag visibility
                #pragma unroll
                for (int rk=0; rk<4; rk++)
                    asm volatile("st.release.cluster.shared::cluster.u32 [%0], %1;"
                                 :: "r"(rf[rk]), "r"((unsigned int)(t+1)) : "memory");
            }
        }
        // shadow work: global stores overlap flag propagation + polling
        if (tid < Dd && g2 == 0){
            int hu = r*48 + u2;
            h_out[(size_t)t*Dd + hu] = hn;
            __nv_bfloat16 hi = __float2bfloat16(hn);
            __nv_bfloat16 lo = __float2bfloat16(hn - __bfloat162float(hi));
            size_t abase = (size_t)(b*Tlen + t)*KEXT + hu;
            g_Aext[abase]      = hi;
            g_Aext[abase+Dd]   = hi;
            g_Aext[abase+2*Dd] = lo;
        }
        if (tid < 48){
            const unsigned int tgt = (unsigned int)(t+1);
            unsigned int v0, v1, v2, v3;
            do {
                asm volatile("ld.acquire.cluster.shared::cta.u32 %0, [%1];"
                             : "=r"(v0) : "r"(pf)      : "memory");
                asm volatile("ld.acquire.cluster.shared::cta.u32 %0, [%1];"
                             : "=r"(v1) : "r"(pf + 4)  : "memory");
                asm volatile("ld.acquire.cluster.shared::cta.u32 %0, [%1];"
                             : "=r"(v2) : "r"(pf + 8)  : "memory");
                asm volatile("ld.acquire.cluster.shared::cta.u32 %0, [%1];"
                             : "=r"(v3) : "r"(pf + 12) : "memory");
            } while (v0 < tgt || v1 < tgt || v2 < tgt || v3 < tgt);
        }
        __syncthreads();
        cur = nxt;
    }
    asm volatile("barrier.cluster.arrive.aligned;\n\t"
                 "barrier.cluster.wait.aligned;" ::: "memory");
}

// ---------------- LayerNorm + fp16 cast for head ----------------
__global__ void ln_kernel(const float* __restrict__ gamma,
                          const float* __restrict__ beta,
                          float* __restrict__ out){
    const int row = blockIdx.x;
    const int tid = threadIdx.x;
    float v = g_h[(size_t)row*Dd + tid];
    float s = v, s2 = v*v;
    #pragma unroll
    for (int o=16;o;o>>=1){
        s  += __shfl_down_sync(0xffffffffu, s,  o);
        s2 += __shfl_down_sync(0xffffffffu, s2, o);
    }
    __shared__ float ws[6], ws2[6];
    __shared__ float mean_s, inv_s;
    int w = tid >> 5, lane = tid & 31;
    if (!lane){ ws[w]=s; ws2[w]=s2; }
    __syncthreads();
    if (tid==0){
        float S=0.f, S2=0.f;
        #pragma unroll
        for (int i=0;i<6;i++){ S+=ws[i]; S2+=ws2[i]; }
        float mu = S * (1.f/Dd);
        float var = S2 * (1.f/Dd) - mu*mu;
        mean_s = mu;
        inv_s  = rsqrtf(var + 1e-5f);
    }
    __syncthreads();
    float y = (v - mean_s) * inv_s * gamma[tid] + beta[tid];
    out[(size_t)row*Dd + tid] = y;
    g_Ahead[(size_t)row*KHEAD + tid] = __float2half_rn(y);
}

// ---------------- launch ----------------
extern "C" void kernel_launch(void* const* d_in, const int* in_sizes, int n_in,
                              void* d_out, int out_size)
{
    const int*   x     = (const int*)  d_in[0];
    const float* tok   = (const float*)d_in[1];
    const float* pos   = (const float*)d_in[2];
    const float* W_ih  = (const float*)d_in[3];
    const float* W_hh  = (const float*)d_in[4];
    const float* b_ih  = (const float*)d_in[5];
    const float* b_hh  = (const float*)d_in[6];
    const float* gamma = (const float*)d_in[7];
    const float* beta  = (const float*)d_in[8];

    float* out_logits = (float*)d_out;
    float* out_h      = (float*)d_out + BTV;

    float *pgx=nullptr;
    __nv_bfloat16 *pAe=nullptr, *pWe=nullptr;
    __half *pAh=nullptr, *pBh=nullptr;
    cudaGetSymbolAddress((void**)&pgx, g_gx);
    cudaGetSymbolAddress((void**)&pAe, g_Aext);
    cudaGetSymbolAddress((void**)&pWe, g_Wext);
    cudaGetSymbolAddress((void**)&pAh, g_Ahead);
    cudaGetSymbolAddress((void**)&pBh, g_Bh);

    cudaFuncSetAttribute((const void*)mma_gemm<9,true>,
        cudaFuncAttributeMaxDynamicSharedMemorySize, GX_SMEM);
    cudaFuncSetAttribute((const void*)head_gemm,
        cudaFuncAttributeMaxDynamicSharedMemorySize, HEAD_SMEM);

    embed_split<<<BT, Dd>>>(x, tok, pos);
    conv_all<<<Vv + Ll*H4d, Dd>>>(tok, W_ih);

    for (int l = 0; l < Ll; l++){
        mma_gemm<9,true><<<dim3(H4d/128, BT/64), 128, GX_SMEM>>>(
            pAe, pWe + (size_t)l*H4d*KEXT,
            b_ih + (size_t)l*H4d, b_hh + (size_t)l*H4d,
            pgx, H4d);
        lstm_kernel<<<dim3(4, Bsz), 384>>>(W_hh + (size_t)l*H4d*Dd);
    }

    ln_kernel<<<BT, Dd>>>(gamma, beta, out_h);

    head_gemm<<<dim3(Vv/128, BT/128), 128, HEAD_SMEM>>>(
        pAh, pBh, out_logits, Vv);
}

// round 16
// speedup vs baseline: 1.7259x; 1.7259x over previous
#include <cuda_runtime.h>
#include <cuda_bf16.h>
#include <cuda_fp16.h>
#include <cstdint>
#include <cmath>

#define Bsz 32
#define Tlen 128
#define Dd 192
#define H4d 768
#define Ll 6
#define Vv 32000
#define BT (Bsz*Tlen)            // 4096
#define BTV ((size_t)BT*(size_t)Vv)
#define KEXT 576                 // bf16 3-way split K (gx GEMMs)
#define KHEAD 192                // plain fp16 head GEMM K

typedef unsigned long long ull;

// ---------------- scratch ----------------
__device__ __align__(128) float g_h[BT*Dd];
__device__ __align__(128) float g_gx[BT*H4d];
__device__ __align__(128) __nv_bfloat16 g_Aext[BT*KEXT];              // [hi|hi|lo]
__device__ __align__(128) __nv_bfloat16 g_Wext[(size_t)Ll*H4d*KEXT];  // [hi|lo|hi]
__device__ __align__(128) __half g_Ahead[(size_t)BT*KHEAD];           // fp16(LN(h))
__device__ __align__(128) __half g_Bh[(size_t)Vv*Dd];                 // fp16(tok)

// ---------------- helpers ----------------
__device__ __forceinline__ uint32_t smem_u32(const void* p){
    uint32_t a;
    asm("{ .reg .u64 t; cvta.to.shared.u64 t, %1; cvt.u32.u64 %0, t; }"
        : "=r"(a) : "l"(p));
    return a;
}
__device__ __forceinline__ float2 unpack2(ull v){
    unsigned int lo, hi;
    asm("mov.b64 {%0, %1}, %2;" : "=r"(lo), "=r"(hi) : "l"(v));
    return make_float2(__uint_as_float(lo), __uint_as_float(hi));
}
__device__ __forceinline__ void fma2(ull &d, ull a, ull b){
    asm("fma.rn.f32x2 %0, %1, %2, %3;" : "=l"(d) : "l"(a), "l"(b), "l"(d));
}
__device__ __forceinline__ void cp16(uint32_t s, const void* g){
    asm volatile("cp.async.cg.shared.global [%0], [%1], 16;" :: "r"(s), "l"(g) : "memory");
}
#define SW128(x) ((x) ^ (((x) >> 3) & 0x70))

__device__ __forceinline__ void ldm4(uint32_t &r0, uint32_t &r1,
                                     uint32_t &r2, uint32_t &r3, uint32_t a){
    asm volatile("ldmatrix.sync.aligned.m8n8.x4.shared.b16 {%0,%1,%2,%3}, [%4];"
        : "=r"(r0), "=r"(r1), "=r"(r2), "=r"(r3) : "r"(a));
}
template<bool HALF>
__device__ __forceinline__ void mma16816(float* d, const uint32_t* a,
                                         uint32_t b0, uint32_t b1){
    if (HALF)
        asm volatile("mma.sync.aligned.m16n8k16.row.col.f32.f16.f16.f32 "
            "{%0,%1,%2,%3}, {%4,%5,%6,%7}, {%8,%9}, {%0,%1,%2,%3};"
            : "+f"(d[0]), "+f"(d[1]), "+f"(d[2]), "+f"(d[3])
            : "r"(a[0]), "r"(a[1]), "r"(a[2]), "r"(a[3]), "r"(b0), "r"(b1));
    else
        asm volatile("mma.sync.aligned.m16n8k16.row.col.f32.bf16.bf16.f32 "
            "{%0,%1,%2,%3}, {%4,%5,%6,%7}, {%8,%9}, {%0,%1,%2,%3};"
            : "+f"(d[0]), "+f"(d[1]), "+f"(d[2]), "+f"(d[3])
            : "r"(a[0]), "r"(a[1]), "r"(a[2]), "r"(a[3]), "r"(b0), "r"(b1));
}

__device__ __forceinline__ float fast_sig(float x){
    float e, r;
    asm("ex2.approx.f32 %0, %1;" : "=f"(e) : "f"(x * -1.4426950408889634f));
    asm("rcp.approx.f32 %0, %1;" : "=f"(r) : "f"(e + 1.0f));
    return r;
}
__device__ __forceinline__ float fast_tanh(float x){
    float e, r;
    asm("ex2.approx.f32 %0, %1;" : "=f"(e) : "f"(x * -2.8853900817779268f));
    asm("rcp.approx.f32 %0, %1;" : "=f"(r) : "f"(e + 1.0f));
    return fmaf(2.f, r, -1.f);
}

// ---------------- embedding + bf16 3-way split [hi|hi|lo] ----------------
__global__ void embed_split(const int* __restrict__ x,
                            const float* __restrict__ tok,
                            const float* __restrict__ pos){
    int row = blockIdx.x;
    int t   = row & (Tlen - 1);
    int c   = threadIdx.x;
    int v   = x[row];
    float a = tok[(size_t)v*Dd + c] + pos[t*Dd + c];
    __nv_bfloat16 hi = __float2bfloat16(a);
    __nv_bfloat16 lo = __float2bfloat16(a - __bfloat162float(hi));
    size_t b = (size_t)row*KEXT;
    g_Aext[b + c] = hi; g_Aext[b + Dd + c] = hi; g_Aext[b + 2*Dd + c] = lo;
}

// ---------------- fused weight conversion (tok->fp16, W_ih->bf16 3-way) ---------
__global__ void conv_all(const float* __restrict__ tok,
                         const float* __restrict__ W_ih){
    int row = blockIdx.x, c = threadIdx.x;
    if (row < Vv){
        g_Bh[(size_t)row*Dd + c] = __float2half_rn(tok[(size_t)row*Dd + c]);
    } else {
        int r2 = row - Vv;
        float a = W_ih[(size_t)r2*Dd + c];
        __nv_bfloat16 hi = __float2bfloat16(a);
        __nv_bfloat16 lo = __float2bfloat16(a - __bfloat162float(hi));
        size_t b = (size_t)r2*KEXT;
        g_Wext[b + c] = hi; g_Wext[b + Dd + c] = lo; g_Wext[b + 2*Dd + c] = hi;
    }
}

// ---------------- gx GEMM (bf16 3-way, K=576): CTA 64x128, 4 warps, 3 CTA/SM ----
#define GXSTAGE 24576
#define GX_SMEM (3*GXSTAGE + 1024)

template<int KCH, bool BIAS>
__global__ __launch_bounds__(128,3) void mma_gemm(
    const void* __restrict__ A, const void* __restrict__ Bw,
    const float* __restrict__ b1, const float* __restrict__ b2,
    float* __restrict__ C, int N)
{
    extern __shared__ char smem_raw[];
    const uint32_t sbase = (smem_u32(smem_raw) + 1023u) & ~1023u;
    const int KA = KCH*64;

    const int t    = threadIdx.x;
    const int lane = t & 31;
    const int wid  = t >> 5;
    const int m0   = blockIdx.y * 64;
    const int n0   = blockIdx.x * 128;
    const int mw   = (wid & 1) * 32;
    const int nw   = (wid >> 1) * 64;

    const char* Ab = (const char*)A;
    const char* Bb = (const char*)Bw;
    uint32_t sAoff[4], gAoff[4];
    #pragma unroll
    for (int i=0;i<4;i++){
        int idx = t + i*128, row = idx>>3, cc = idx&7;
        sAoff[i] = SW128((uint32_t)(row*128 + cc*16));
        gAoff[i] = (uint32_t)((m0+row)*KA*2 + cc*16);
    }
    uint32_t sBoff[8], gBoff[8];
    #pragma unroll
    for (int i=0;i<8;i++){
        int idx = t + i*128, row = idx>>3, cc = idx&7;
        sBoff[i] = 8192u + SW128((uint32_t)(row*128 + cc*16));
        gBoff[i] = (uint32_t)((n0+row)*KA*2 + cc*16);
    }

    uint32_t aOff[2], bOff[4];
    {
        int r = lane & 15, hc = (lane >> 4) * 16;
        #pragma unroll
        for (int mt=0; mt<2; mt++)
            aOff[mt] = SW128((uint32_t)((mw + mt*16 + r)*128 + hc));
        #pragma unroll
        for (int p=0; p<4; p++)
            bOff[p] = 8192u + SW128((uint32_t)((nw + p*16 + r)*128 + hc));
    }

    float acc[2][8][4];
    #pragma unroll
    for (int i=0;i<2;i++)
        #pragma unroll
        for (int j=0;j<8;j++)
            #pragma unroll
            for (int k=0;k<4;k++) acc[i][j][k] = 0.f;

    #pragma unroll
    for (int s=0;s<2;s++){
        uint32_t sb = sbase + s*GXSTAGE;
        uint32_t ka = (uint32_t)s*128;
        #pragma unroll
        for (int i=0;i<4;i++) cp16(sb + sAoff[i], Ab + gAoff[i] + ka);
        #pragma unroll
        for (int i=0;i<8;i++) cp16(sb + sBoff[i], Bb + gBoff[i] + ka);
        asm volatile("cp.async.commit_group;" ::: "memory");
    }

    int sidx = 0;
    #pragma unroll 1
    for (int k0 = 0; k0 < KCH; k0++){
        if (k0 == KCH-1) asm volatile("cp.async.wait_group 0;" ::: "memory");
        else             asm volatile("cp.async.wait_group 1;" ::: "memory");
        __syncthreads();

        if (k0 + 2 < KCH){
            int s2 = sidx + 2; if (s2 >= 3) s2 -= 3;
            uint32_t sb = sbase + s2*GXSTAGE;
            uint32_t ka = (uint32_t)(k0+2)*128;
            #pragma unroll
            for (int i=0;i<4;i++) cp16(sb + sAoff[i], Ab + gAoff[i] + ka);
            #pragma unroll
            for (int i=0;i<8;i++) cp16(sb + sBoff[i], Bb + gBoff[i] + ka);
            asm volatile("cp.async.commit_group;" ::: "memory");
        }

        const uint32_t sb = sbase + sidx*GXSTAGE;
        #pragma unroll
        for (int ks=0; ks<4; ks++){
            const uint32_t kx = ks*32;
            uint32_t a[2][4];
            ldm4(a[0][0], a[0][1], a[0][2], a[0][3], sb + (aOff[0]^kx));
            ldm4(a[1][0], a[1][1], a[1][2], a[1][3], sb + (aOff[1]^kx));
            #pragma unroll
            for (int p=0; p<4; p++){
                uint32_t r0,r1,r2,r3;
                ldm4(r0, r1, r2, r3, sb + (bOff[p]^kx));
                mma16816<false>(acc[0][2*p],   a[0], r0, r2);
                mma16816<false>(acc[0][2*p+1], a[0], r1, r3);
                mma16816<false>(acc[1][2*p],   a[1], r0, r2);
                mma16816<false>(acc[1][2*p+1], a[1], r1, r3);
            }
        }
        sidx++; if (sidx == 3) sidx = 0;
    }

    const int g  = lane >> 2;
    const int tc = (lane & 3) * 2;
    #pragma unroll
    for (int mt=0; mt<2; mt++){
        const int row = m0 + mw + mt*16 + g;
        #pragma unroll
        for (int nt=0; nt<8; nt++){
            const int col = n0 + nw + (nt>>1)*16 + (nt&1)*8 + tc;
            float bb0 = 0.f, bb1 = 0.f;
            if (BIAS){ bb0 = b1[col] + b2[col]; bb1 = b1[col+1] + b2[col+1]; }
            float2 v0 = make_float2(acc[mt][nt][0] + bb0, acc[mt][nt][1] + bb1);
            float2 v1 = make_float2(acc[mt][nt][2] + bb0, acc[mt][nt][3] + bb1);
            *reinterpret_cast<float2*>(C + (size_t)row*N + col)     = v0;
            *reinterpret_cast<float2*>(C + (size_t)(row+8)*N + col) = v1;
        }
    }
}

// ---------------- head GEMM: fp16 K=192, A+B fully smem-resident -----------
#define HEAD_SMEM (98304 + 1024)

__global__ __launch_bounds__(128,2) void head_gemm(
    const __half* __restrict__ A, const __half* __restrict__ Bw,
    float* __restrict__ C, int N)
{
    extern __shared__ char smem_raw[];
    const uint32_t sbase = (smem_u32(smem_raw) + 1023u) & ~1023u;
    const uint32_t sA = sbase;
    const uint32_t sB = sbase + 49152;

    const int t    = threadIdx.x;
    const int lane = t & 31;
    const int wid  = t >> 5;
    const int m0   = blockIdx.y * 128;
    const int n0   = blockIdx.x * 128;
    const int wm   = (wid & 1) * 64;
    const int wn   = (wid >> 1) * 64;

    #pragma unroll
    for (int i=0;i<24;i++){
        int idx = t + i*128;
        int c = idx>>10, rem = idx&1023, row = rem>>3, cc = rem&7;
        uint32_t sw = SW128((uint32_t)(row*128 + cc*16));
        cp16(sA + c*16384 + sw,
             (const char*)A  + (size_t)(m0+row)*(KHEAD*2) + c*128 + cc*16);
        cp16(sB + c*16384 + sw,
             (const char*)Bw + (size_t)(n0+row)*(Dd*2)    + c*128 + cc*16);
    }
    asm volatile("cp.async.commit_group;" ::: "memory");

    uint32_t aOff[4], bOff[4];
    {
        int r = lane & 15, hc = (lane >> 4) * 16;
        #pragma unroll
        for (int mt=0; mt<4; mt++)
            aOff[mt] = SW128((uint32_t)((wm + mt*16 + r)*128 + hc));
        #pragma unroll
        for (int p=0; p<4; p++)
            bOff[p] = SW128((uint32_t)((wn + p*16 + r)*128 + hc));
    }

    float acc[4][8][4];
    #pragma unroll
    for (int i=0;i<4;i++)
        #pragma unroll
        for (int j=0;j<8;j++)
            #pragma unroll
            for (int k=0;k<4;k++) acc[i][j][k] = 0.f;

    asm volatile("cp.async.wait_group 0;" ::: "memory");
    __syncthreads();

    #pragma unroll
    for (int k0 = 0; k0 < 3; k0++){
        const uint32_t sbA = sA + k0*16384;
        const uint32_t sbB = sB + k0*16384;
        #pragma unroll
        for (int ks=0; ks<4; ks++){
            const uint32_t kx = ks*32;
            uint32_t a[4][4], b[4][4];
            #pragma unroll
            for (int mt=0; mt<4; mt++)
                ldm4(a[mt][0], a[mt][1], a[mt][2], a[mt][3], sbA + (aOff[mt]^kx));
            #pragma unroll
            for (int p=0; p<4; p++)
                ldm4(b[p][0], b[p][1], b[p][2], b[p][3], sbB + (bOff[p]^kx));
            #pragma unroll
            for (int p=0; p<4; p++)
                #pragma unroll
                for (int mt=0; mt<4; mt++){
                    mma16816<true>(acc[mt][2*p],   a[mt], b[p][0], b[p][2]);
                    mma16816<true>(acc[mt][2*p+1], a[mt], b[p][1], b[p][3]);
                }
        }
    }

    const int g  = lane >> 2;
    const int tc = (lane & 3) * 2;
    #pragma unroll
    for (int mt=0; mt<4; mt++){
        const int row = m0 + wm + mt*16 + g;
        #pragma unroll
        for (int nt=0; nt<8; nt++){
            const int col = n0 + wn + (nt>>1)*16 + (nt&1)*8 + tc;
            float2 v0 = make_float2(acc[mt][nt][0], acc[mt][nt][1]);
            float2 v1 = make_float2(acc[mt][nt][2], acc[mt][nt][3]);
            *reinterpret_cast<float2*>(C + (size_t)row*N + col)     = v0;
            *reinterpret_cast<float2*>(C + (size_t)(row+8)*N + col) = v1;
        }
    }
}

// ---------------- LSTM: r12 winner — split arrive/wait, shadowed global stores --
__global__ __launch_bounds__(384,1) __cluster_dims__(4,1,1)
void lstm_kernel(const float* __restrict__ Wl)
{
    __shared__ float h_buf[2][Dd];
    __shared__ float partial[Dd];
    __shared__ float gsm[Dd];

    const int r   = blockIdx.x;
    const int b   = blockIdx.y;
    const int tid = threadIdx.x;
    const int half = (tid >= Dd) ? 1 : 0;
    const int j    = tid - half*Dd;
    const int q    = j / 48;
    const int u    = j - q*48;
    const int row_g = q*Dd + r*48 + u;

    ull w2[48];
    const ull* wp = (const ull*)(Wl + (size_t)row_g*Dd + half*96);
    #pragma unroll
    for (int k=0;k<48;k++) w2[k] = wp[k];

    for (int i = tid; i < 2*Dd; i += 384) (&h_buf[0][0])[i] = 0.f;
    asm volatile("barrier.cluster.arrive.aligned;\n\t"
                 "barrier.cluster.wait.aligned;" ::: "memory");

    const float* gx_base = g_gx + (size_t)b*Tlen*H4d + row_g;
    float*       h_out   = g_h  + (size_t)b*Tlen*Dd;
    const uint32_t hbuf_addr = smem_u32(&h_buf[0][0]);

    const int u2 = tid >> 2;
    const int g2 = tid & 3;
    uint32_t ra[2][4];
    if (tid < Dd && g2 == 0){
        uint32_t la0 = hbuf_addr + (uint32_t)(r*48 + u2)*4u;
        #pragma unroll
        for (int rk=0; rk<4; rk++){
            asm("mapa.shared::cluster.u32 %0, %1, %2;" : "=r"(ra[0][rk]) : "r"(la0),        "r"(rk));
            asm("mapa.shared::cluster.u32 %0, %1, %2;" : "=r"(ra[1][rk]) : "r"(la0 + 768u), "r"(rk));
        }
    }

    float c = 0.f;
    float gxv = (!half) ? gx_base[0] : 0.f;

    int cur = 0;
    #pragma unroll 1
    for (int t = 0; t < Tlen; t++){
        const ull* hp = (const ull*)(&h_buf[cur][half*96]);
        ull a0=0ULL, a1=0ULL, a2=0ULL, a3=0ULL;
        #pragma unroll
        for (int k=0;k<48;k+=4){
            fma2(a0, w2[k+0], hp[k+0]);
            fma2(a1, w2[k+1], hp[k+1]);
            fma2(a2, w2[k+2], hp[k+2]);
            fma2(a3, w2[k+3], hp[k+3]);
        }
        float2 f0=unpack2(a0), f1=unpack2(a1), f2=unpack2(a2), f3=unpack2(a3);
        float acc = ((f0.x+f0.y)+(f1.x+f1.y)) + ((f2.x+f2.y)+(f3.x+f3.y));

        if (half) partial[j] = acc;
        __syncthreads();
        if (!half) gsm[j] = acc + partial[j] + gxv;
        __syncthreads();
        if (!half){
            int tn = (t+1 < Tlen) ? t+1 : t;
            gxv = gx_base[(size_t)tn*H4d];
        }

        const int nxt = cur ^ 1;
        float hn = 0.f;
        if (tid < Dd){
            float val = gsm[g2*48 + u2];
            float nl  = (g2 == 2) ? fast_tanh(val) : fast_sig(val);
            const int lb = (tid & 31) & ~3;
            float fi  = __shfl_sync(0xffffffffu, nl, lb);
            float ff  = __shfl_sync(0xffffffffu, nl, lb|1);
            float fgg = __shfl_sync(0xffffffffu, nl, lb|2);
            float fo  = __shfl_sync(0xffffffffu, nl, lb|3);
            if (g2 == 0){
                c = ff*c + fi*fgg;
                hn = fo * fast_tanh(c);
                #pragma unroll
                for (int rk=0; rk<4; rk++)
                    asm volatile("st.shared::cluster.f32 [%0], %1;"
                                 :: "r"(ra[nxt][rk]), "f"(hn) : "memory");
            }
        }
        // arrive (release) right after remote h stores; global stores overlap wait
        asm volatile("barrier.cluster.arrive;" ::: "memory");
        if (tid < Dd && g2 == 0){
            int hu = r*48 + u2;
            h_out[(size_t)t*Dd + hu] = hn;
            __nv_bfloat16 hi = __float2bfloat16(hn);
            __nv_bfloat16 lo = __float2bfloat16(hn - __bfloat162float(hi));
            size_t abase = (size_t)(b*Tlen + t)*KEXT + hu;
            g_Aext[abase]      = hi;
            g_Aext[abase+Dd]   = hi;
            g_Aext[abase+2*Dd] = lo;
        }
        asm volatile("barrier.cluster.wait;" ::: "memory");
        cur = nxt;
    }
}

// ---------------- LayerNorm + fp16 cast for head ----------------
__global__ void ln_kernel(const float* __restrict__ gamma,
                          const float* __restrict__ beta,
                          float* __restrict__ out){
    const int row = blockIdx.x;
    const int tid = threadIdx.x;
    float v = g_h[(size_t)row*Dd + tid];
    float s = v, s2 = v*v;
    #pragma unroll
    for (int o=16;o;o>>=1){
        s  += __shfl_down_sync(0xffffffffu, s,  o);
        s2 += __shfl_down_sync(0xffffffffu, s2, o);
    }
    __shared__ float ws[6], ws2[6];
    __shared__ float mean_s, inv_s;
    int w = tid >> 5, lane = tid & 31;
    if (!lane){ ws[w]=s; ws2[w]=s2; }
    __syncthreads();
    if (tid==0){
        float S=0.f, S2=0.f;
        #pragma unroll
        for (int i=0;i<6;i++){ S+=ws[i]; S2+=ws2[i]; }
        float mu = S * (1.f/Dd);
        float var = S2 * (1.f/Dd) - mu*mu;
        mean_s = mu;
        inv_s  = rsqrtf(var + 1e-5f);
    }
    __syncthreads();
    float y = (v - mean_s) * inv_s * gamma[tid] + beta[tid];
    out[(size_t)row*Dd + tid] = y;
    g_Ahead[(size_t)row*KHEAD + tid] = __float2half_rn(y);
}

// ---------------- launch ----------------
extern "C" void kernel_launch(void* const* d_in, const int* in_sizes, int n_in,
                              void* d_out, int out_size)
{
    const int*   x     = (const int*)  d_in[0];
    const float* tok   = (const float*)d_in[1];
    const float* pos   = (const float*)d_in[2];
    const float* W_ih  = (const float*)d_in[3];
    const float* W_hh  = (const float*)d_in[4];
    const float* b_ih  = (const float*)d_in[5];
    const float* b_hh  = (const float*)d_in[6];
    const float* gamma = (const float*)d_in[7];
    const float* beta  = (const float*)d_in[8];

    float* out_logits = (float*)d_out;
    float* out_h      = (float*)d_out + BTV;

    float *pgx=nullptr;
    __nv_bfloat16 *pAe=nullptr, *pWe=nullptr;
    __half *pAh=nullptr, *pBh=nullptr;
    cudaGetSymbolAddress((void**)&pgx, g_gx);
    cudaGetSymbolAddress((void**)&pAe, g_Aext);
    cudaGetSymbolAddress((void**)&pWe, g_Wext);
    cudaGetSymbolAddress((void**)&pAh, g_Ahead);
    cudaGetSymbolAddress((void**)&pBh, g_Bh);

    cudaFuncSetAttribute((const void*)mma_gemm<9,true>,
        cudaFuncAttributeMaxDynamicSharedMemorySize, GX_SMEM);
    cudaFuncSetAttribute((const void*)head_gemm,
        cudaFuncAttributeMaxDynamicSharedMemorySize, HEAD_SMEM);

    embed_split<<<BT, Dd>>>(x, tok, pos);
    conv_all<<<Vv + Ll*H4d, Dd>>>(tok, W_ih);

    for (int l = 0; l < Ll; l++){
        mma_gemm<9,true><<<dim3(H4d/128, BT/64), 128, GX_SMEM>>>(
            pAe, pWe + (size_t)l*H4d*KEXT,
            b_ih + (size_t)l*H4d, b_hh + (size_t)l*H4d,
            pgx, H4d);
        lstm_kernel<<<dim3(4, Bsz), 384>>>(W_hh + (size_t)l*H4d*Dd);
    }

    ln_kernel<<<BT, Dd>>>(gamma, beta, out_h);

    head_gemm<<<dim3(Vv/128, BT/128), 128, HEAD_SMEM>>>(
        pAh, pBh, out_logits, Vv);
}

// round 17
// speedup vs baseline: 1.7317x; 1.0034x over previous
#include <cuda_runtime.h>
#include <cuda_bf16.h>
#include <cuda_fp16.h>
#include <cstdint>
#include <cmath>

#define Bsz 32
#define Tlen 128
#define Dd 192
#define H4d 768
#define Ll 6
#define Vv 32000
#define BT (Bsz*Tlen)            // 4096
#define BTV ((size_t)BT*(size_t)Vv)
#define KEXT 576                 // bf16 3-way split K (gx GEMMs)
#define KHEAD 192                // plain fp16 head GEMM K

typedef unsigned long long ull;

// ---------------- scratch ----------------
__device__ __align__(128) float g_h[BT*Dd];
__device__ __align__(128) float g_gx[BT*H4d];
__device__ __align__(128) __nv_bfloat16 g_Aext[BT*KEXT];              // [hi|hi|lo]
__device__ __align__(128) __nv_bfloat16 g_Wext[(size_t)Ll*H4d*KEXT];  // [hi|lo|hi]
__device__ __align__(128) __half g_Ahead[(size_t)BT*KHEAD];           // fp16(LN(h))
__device__ __align__(128) __half g_Bh[(size_t)Vv*Dd];                 // fp16(tok)

// ---------------- helpers ----------------
__device__ __forceinline__ uint32_t smem_u32(const void* p){
    uint32_t a;
    asm("{ .reg .u64 t; cvta.to.shared.u64 t, %1; cvt.u32.u64 %0, t; }"
        : "=r"(a) : "l"(p));
    return a;
}
__device__ __forceinline__ float2 unpack2(ull v){
    unsigned int lo, hi;
    asm("mov.b64 {%0, %1}, %2;" : "=r"(lo), "=r"(hi) : "l"(v));
    return make_float2(__uint_as_float(lo), __uint_as_float(hi));
}
__device__ __forceinline__ void fma2(ull &d, ull a, ull b){
    asm("fma.rn.f32x2 %0, %1, %2, %3;" : "=l"(d) : "l"(a), "l"(b), "l"(d));
}
__device__ __forceinline__ void cp16(uint32_t s, const void* g){
    asm volatile("cp.async.cg.shared.global [%0], [%1], 16;" :: "r"(s), "l"(g) : "memory");
}
#define SW128(x) ((x) ^ (((x) >> 3) & 0x70))

__device__ __forceinline__ void ldm4(uint32_t &r0, uint32_t &r1,
                                     uint32_t &r2, uint32_t &r3, uint32_t a){
    asm volatile("ldmatrix.sync.aligned.m8n8.x4.shared.b16 {%0,%1,%2,%3}, [%4];"
        : "=r"(r0), "=r"(r1), "=r"(r2), "=r"(r3) : "r"(a));
}
template<bool HALF>
__device__ __forceinline__ void mma16816(float* d, const uint32_t* a,
                                         uint32_t b0, uint32_t b1){
    if (HALF)
        asm volatile("mma.sync.aligned.m16n8k16.row.col.f32.f16.f16.f32 "
            "{%0,%1,%2,%3}, {%4,%5,%6,%7}, {%8,%9}, {%0,%1,%2,%3};"
            : "+f"(d[0]), "+f"(d[1]), "+f"(d[2]), "+f"(d[3])
            : "r"(a[0]), "r"(a[1]), "r"(a[2]), "r"(a[3]), "r"(b0), "r"(b1));
    else
        asm volatile("mma.sync.aligned.m16n8k16.row.col.f32.bf16.bf16.f32 "
            "{%0,%1,%2,%3}, {%4,%5,%6,%7}, {%8,%9}, {%0,%1,%2,%3};"
            : "+f"(d[0]), "+f"(d[1]), "+f"(d[2]), "+f"(d[3])
            : "r"(a[0]), "r"(a[1]), "r"(a[2]), "r"(a[3]), "r"(b0), "r"(b1));
}

__device__ __forceinline__ float fast_sig(float x){
    float e, r;
    asm("ex2.approx.f32 %0, %1;" : "=f"(e) : "f"(x * -1.4426950408889634f));
    asm("rcp.approx.f32 %0, %1;" : "=f"(r) : "f"(e + 1.0f));
    return r;
}
__device__ __forceinline__ float fast_tanh(float x){
    float e, r;
    asm("ex2.approx.f32 %0, %1;" : "=f"(e) : "f"(x * -2.8853900817779268f));
    asm("rcp.approx.f32 %0, %1;" : "=f"(r) : "f"(e + 1.0f));
    return fmaf(2.f, r, -1.f);
}

// ---------------- embedding + bf16 3-way split [hi|hi|lo] ----------------
__global__ void embed_split(const int* __restrict__ x,
                            const float* __restrict__ tok,
                            const float* __restrict__ pos){
    int row = blockIdx.x;
    int t   = row & (Tlen - 1);
    int c   = threadIdx.x;
    int v   = x[row];
    float a = tok[(size_t)v*Dd + c] + pos[t*Dd + c];
    __nv_bfloat16 hi = __float2bfloat16(a);
    __nv_bfloat16 lo = __float2bfloat16(a - __bfloat162float(hi));
    size_t b = (size_t)row*KEXT;
    g_Aext[b + c] = hi; g_Aext[b + Dd + c] = hi; g_Aext[b + 2*Dd + c] = lo;
}

// ---------------- fused weight conversion (tok->fp16, W_ih->bf16 3-way) ---------
__global__ void conv_all(const float* __restrict__ tok,
                         const float* __restrict__ W_ih){
    int row = blockIdx.x, c = threadIdx.x;
    if (row < Vv){
        g_Bh[(size_t)row*Dd + c] = __float2half_rn(tok[(size_t)row*Dd + c]);
    } else {
        int r2 = row - Vv;
        float a = W_ih[(size_t)r2*Dd + c];
        __nv_bfloat16 hi = __float2bfloat16(a);
        __nv_bfloat16 lo = __float2bfloat16(a - __bfloat162float(hi));
        size_t b = (size_t)r2*KEXT;
        g_Wext[b + c] = hi; g_Wext[b + Dd + c] = lo; g_Wext[b + 2*Dd + c] = hi;
    }
}

// ---------------- gx GEMM (bf16 3-way, K=576): CTA 64x128, 4 warps, 3 CTA/SM ----
#define GXSTAGE 24576
#define GX_SMEM (3*GXSTAGE + 1024)

template<int KCH, bool BIAS>
__global__ __launch_bounds__(128,3) void mma_gemm(
    const void* __restrict__ A, const void* __restrict__ Bw,
    const float* __restrict__ b1, const float* __restrict__ b2,
    float* __restrict__ C, int N)
{
    extern __shared__ char smem_raw[];
    const uint32_t sbase = (smem_u32(smem_raw) + 1023u) & ~1023u;
    const int KA = KCH*64;

    const int t    = threadIdx.x;
    const int lane = t & 31;
    const int wid  = t >> 5;
    const int m0   = blockIdx.y * 64;
    const int n0   = blockIdx.x * 128;
    const int mw   = (wid & 1) * 32;
    const int nw   = (wid >> 1) * 64;

    const char* Ab = (const char*)A;
    const char* Bb = (const char*)Bw;
    uint32_t sAoff[4], gAoff[4];
    #pragma unroll
    for (int i=0;i<4;i++){
        int idx = t + i*128, row = idx>>3, cc = idx&7;
        sAoff[i] = SW128((uint32_t)(row*128 + cc*16));
        gAoff[i] = (uint32_t)((m0+row)*KA*2 + cc*16);
    }
    uint32_t sBoff[8], gBoff[8];
    #pragma unroll
    for (int i=0;i<8;i++){
        int idx = t + i*128, row = idx>>3, cc = idx&7;
        sBoff[i] = 8192u + SW128((uint32_t)(row*128 + cc*16));
        gBoff[i] = (uint32_t)((n0+row)*KA*2 + cc*16);
    }

    uint32_t aOff[2], bOff[4];
    {
        int r = lane & 15, hc = (lane >> 4) * 16;
        #pragma unroll
        for (int mt=0; mt<2; mt++)
            aOff[mt] = SW128((uint32_t)((mw + mt*16 + r)*128 + hc));
        #pragma unroll
        for (int p=0; p<4; p++)
            bOff[p] = 8192u + SW128((uint32_t)((nw + p*16 + r)*128 + hc));
    }

    float acc[2][8][4];
    #pragma unroll
    for (int i=0;i<2;i++)
        #pragma unroll
        for (int j=0;j<8;j++)
            #pragma unroll
            for (int k=0;k<4;k++) acc[i][j][k] = 0.f;

    #pragma unroll
    for (int s=0;s<2;s++){
        uint32_t sb = sbase + s*GXSTAGE;
        uint32_t ka = (uint32_t)s*128;
        #pragma unroll
        for (int i=0;i<4;i++) cp16(sb + sAoff[i], Ab + gAoff[i] + ka);
        #pragma unroll
        for (int i=0;i<8;i++) cp16(sb + sBoff[i], Bb + gBoff[i] + ka);
        asm volatile("cp.async.commit_group;" ::: "memory");
    }

    int sidx = 0;
    #pragma unroll 1
    for (int k0 = 0; k0 < KCH; k0++){
        if (k0 == KCH-1) asm volatile("cp.async.wait_group 0;" ::: "memory");
        else             asm volatile("cp.async.wait_group 1;" ::: "memory");
        __syncthreads();

        if (k0 + 2 < KCH){
            int s2 = sidx + 2; if (s2 >= 3) s2 -= 3;
            uint32_t sb = sbase + s2*GXSTAGE;
            uint32_t ka = (uint32_t)(k0+2)*128;
            #pragma unroll
            for (int i=0;i<4;i++) cp16(sb + sAoff[i], Ab + gAoff[i] + ka);
            #pragma unroll
            for (int i=0;i<8;i++) cp16(sb + sBoff[i], Bb + gBoff[i] + ka);
            asm volatile("cp.async.commit_group;" ::: "memory");
        }

        const uint32_t sb = sbase + sidx*GXSTAGE;
        #pragma unroll
        for (int ks=0; ks<4; ks++){
            const uint32_t kx = ks*32;
            uint32_t a[2][4];
            ldm4(a[0][0], a[0][1], a[0][2], a[0][3], sb + (aOff[0]^kx));
            ldm4(a[1][0], a[1][1], a[1][2], a[1][3], sb + (aOff[1]^kx));
            #pragma unroll
            for (int p=0; p<4; p++){
                uint32_t r0,r1,r2,r3;
                ldm4(r0, r1, r2, r3, sb + (bOff[p]^kx));
                mma16816<false>(acc[0][2*p],   a[0], r0, r2);
                mma16816<false>(acc[0][2*p+1], a[0], r1, r3);
                mma16816<false>(acc[1][2*p],   a[1], r0, r2);
                mma16816<false>(acc[1][2*p+1], a[1], r1, r3);
            }
        }
        sidx++; if (sidx == 3) sidx = 0;
    }

    const int g  = lane >> 2;
    const int tc = (lane & 3) * 2;
    #pragma unroll
    for (int mt=0; mt<2; mt++){
        const int row = m0 + mw + mt*16 + g;
        #pragma unroll
        for (int nt=0; nt<8; nt++){
            const int col = n0 + nw + (nt>>1)*16 + (nt&1)*8 + tc;
            float bb0 = 0.f, bb1 = 0.f;
            if (BIAS){ bb0 = b1[col] + b2[col]; bb1 = b1[col+1] + b2[col+1]; }
            float2 v0 = make_float2(acc[mt][nt][0] + bb0, acc[mt][nt][1] + bb1);
            float2 v1 = make_float2(acc[mt][nt][2] + bb0, acc[mt][nt][3] + bb1);
            *reinterpret_cast<float2*>(C + (size_t)row*N + col)     = v0;
            *reinterpret_cast<float2*>(C + (size_t)(row+8)*N + col) = v1;
        }
    }
}

// ---------------- head GEMM: fp16 K=192, A+B fully smem-resident -----------
#define HEAD_SMEM (98304 + 1024)

__global__ __launch_bounds__(128,2) void head_gemm(
    const __half* __restrict__ A, const __half* __restrict__ Bw,
    float* __restrict__ C, int N)
{
    extern __shared__ char smem_raw[];
    const uint32_t sbase = (smem_u32(smem_raw) + 1023u) & ~1023u;
    const uint32_t sA = sbase;
    const uint32_t sB = sbase + 49152;

    const int t    = threadIdx.x;
    const int lane = t & 31;
    const int wid  = t >> 5;
    const int m0   = blockIdx.y * 128;
    const int n0   = blockIdx.x * 128;
    const int wm   = (wid & 1) * 64;
    const int wn   = (wid >> 1) * 64;

    #pragma unroll
    for (int i=0;i<24;i++){
        int idx = t + i*128;
        int c = idx>>10, rem = idx&1023, row = rem>>3, cc = rem&7;
        uint32_t sw = SW128((uint32_t)(row*128 + cc*16));
        cp16(sA + c*16384 + sw,
             (const char*)A  + (size_t)(m0+row)*(KHEAD*2) + c*128 + cc*16);
        cp16(sB + c*16384 + sw,
             (const char*)Bw + (size_t)(n0+row)*(Dd*2)    + c*128 + cc*16);
    }
    asm volatile("cp.async.commit_group;" ::: "memory");

    uint32_t aOff[4], bOff[4];
    {
        int r = lane & 15, hc = (lane >> 4) * 16;
        #pragma unroll
        for (int mt=0; mt<4; mt++)
            aOff[mt] = SW128((uint32_t)((wm + mt*16 + r)*128 + hc));
        #pragma unroll
        for (int p=0; p<4; p++)
            bOff[p] = SW128((uint32_t)((wn + p*16 + r)*128 + hc));
    }

    float acc[4][8][4];
    #pragma unroll
    for (int i=0;i<4;i++)
        #pragma unroll
        for (int j=0;j<8;j++)
            #pragma unroll
            for (int k=0;k<4;k++) acc[i][j][k] = 0.f;

    asm volatile("cp.async.wait_group 0;" ::: "memory");
    __syncthreads();

    #pragma unroll
    for (int k0 = 0; k0 < 3; k0++){
        const uint32_t sbA = sA + k0*16384;
        const uint32_t sbB = sB + k0*16384;
        #pragma unroll
        for (int ks=0; ks<4; ks++){
            const uint32_t kx = ks*32;
            uint32_t a[4][4], b[4][4];
            #pragma unroll
            for (int mt=0; mt<4; mt++)
                ldm4(a[mt][0], a[mt][1], a[mt][2], a[mt][3], sbA + (aOff[mt]^kx));
            #pragma unroll
            for (int p=0; p<4; p++)
                ldm4(b[p][0], b[p][1], b[p][2], b[p][3], sbB + (bOff[p]^kx));
            #pragma unroll
            for (int p=0; p<4; p++)
                #pragma unroll
                for (int mt=0; mt<4; mt++){
                    mma16816<true>(acc[mt][2*p],   a[mt], b[p][0], b[p][2]);
                    mma16816<true>(acc[mt][2*p+1], a[mt], b[p][1], b[p][3]);
                }
        }
    }

    const int g  = lane >> 2;
    const int tc = (lane & 3) * 2;
    #pragma unroll
    for (int mt=0; mt<4; mt++){
        const int row = m0 + wm + mt*16 + g;
        #pragma unroll
        for (int nt=0; nt<8; nt++){
            const int col = n0 + wn + (nt>>1)*16 + (nt&1)*8 + tc;
            float2 v0 = make_float2(acc[mt][nt][0], acc[mt][nt][1]);
            float2 v1 = make_float2(acc[mt][nt][2], acc[mt][nt][3]);
            *reinterpret_cast<float2*>(C + (size_t)row*N + col)     = v0;
            *reinterpret_cast<float2*>(C + (size_t)(row+8)*N + col) = v1;
        }
    }
}

// ---------------- LSTM: r12 winner + dead-store elimination ---------------------
// LAST=false (layers 0-4): write only g_Aext (next layer's gx input).
// LAST=true  (layer 5):    write only g_h (LayerNorm input).
template<bool LAST>
__global__ __launch_bounds__(384,1) __cluster_dims__(4,1,1)
void lstm_kernel(const float* __restrict__ Wl)
{
    __shared__ float h_buf[2][Dd];
    __shared__ float partial[Dd];
    __shared__ float gsm[Dd];

    const int r   = blockIdx.x;
    const int b   = blockIdx.y;
    const int tid = threadIdx.x;
    const int half = (tid >= Dd) ? 1 : 0;
    const int j    = tid - half*Dd;
    const int q    = j / 48;
    const int u    = j - q*48;
    const int row_g = q*Dd + r*48 + u;

    ull w2[48];
    const ull* wp = (const ull*)(Wl + (size_t)row_g*Dd + half*96);
    #pragma unroll
    for (int k=0;k<48;k++) w2[k] = wp[k];

    for (int i = tid; i < 2*Dd; i += 384) (&h_buf[0][0])[i] = 0.f;
    asm volatile("barrier.cluster.arrive.aligned;\n\t"
                 "barrier.cluster.wait.aligned;" ::: "memory");

    const float* gx_base = g_gx + (size_t)b*Tlen*H4d + row_g;
    float*       h_out   = g_h  + (size_t)b*Tlen*Dd;
    const uint32_t hbuf_addr = smem_u32(&h_buf[0][0]);

    const int u2 = tid >> 2;
    const int g2 = tid & 3;
    uint32_t ra[2][4];
    if (tid < Dd && g2 == 0){
        uint32_t la0 = hbuf_addr + (uint32_t)(r*48 + u2)*4u;
        #pragma unroll
        for (int rk=0; rk<4; rk++){
            asm("mapa.shared::cluster.u32 %0, %1, %2;" : "=r"(ra[0][rk]) : "r"(la0),        "r"(rk));
            asm("mapa.shared::cluster.u32 %0, %1, %2;" : "=r"(ra[1][rk]) : "r"(la0 + 768u), "r"(rk));
        }
    }

    float c = 0.f;
    float gxv = (!half) ? gx_base[0] : 0.f;

    int cur = 0;
    #pragma unroll 1
    for (int t = 0; t < Tlen; t++){
        const ull* hp = (const ull*)(&h_buf[cur][half*96]);
        ull a0=0ULL, a1=0ULL, a2=0ULL, a3=0ULL;
        #pragma unroll
        for (int k=0;k<48;k+=4){
            fma2(a0, w2[k+0], hp[k+0]);
            fma2(a1, w2[k+1], hp[k+1]);
            fma2(a2, w2[k+2], hp[k+2]);
            fma2(a3, w2[k+3], hp[k+3]);
        }
        float2 f0=unpack2(a0), f1=unpack2(a1), f2=unpack2(a2), f3=unpack2(a3);
        float acc = ((f0.x+f0.y)+(f1.x+f1.y)) + ((f2.x+f2.y)+(f3.x+f3.y));

        if (half) partial[j] = acc;
        __syncthreads();
        if (!half) gsm[j] = acc + partial[j] + gxv;
        __syncthreads();
        if (!half){
            int tn = (t+1 < Tlen) ? t+1 : t;
            gxv = gx_base[(size_t)tn*H4d];
        }

        const int nxt = cur ^ 1;
        float hn = 0.f;
        if (tid < Dd){
            float val = gsm[g2*48 + u2];
            float nl  = (g2 == 2) ? fast_tanh(val) : fast_sig(val);
            const int lb = (tid & 31) & ~3;
            float fi  = __shfl_sync(0xffffffffu, nl, lb);
            float ff  = __shfl_sync(0xffffffffu, nl, lb|1);
            float fgg = __shfl_sync(0xffffffffu, nl, lb|2);
            float fo  = __shfl_sync(0xffffffffu, nl, lb|3);
            if (g2 == 0){
                c = ff*c + fi*fgg;
                hn = fo * fast_tanh(c);
                #pragma unroll
                for (int rk=0; rk<4; rk++)
                    asm volatile("st.shared::cluster.f32 [%0], %1;"
                                 :: "r"(ra[nxt][rk]), "f"(hn) : "memory");
            }
        }
        // arrive (release) right after remote h stores; global stores overlap wait
        asm volatile("barrier.cluster.arrive;" ::: "memory");
        if (tid < Dd && g2 == 0){
            int hu = r*48 + u2;
            if (LAST){
                h_out[(size_t)t*Dd + hu] = hn;          // only LayerNorm consumes
            } else {
                __nv_bfloat16 hi = __float2bfloat16(hn); // only next gx consumes
                __nv_bfloat16 lo = __float2bfloat16(hn - __bfloat162float(hi));
                size_t abase = (size_t)(b*Tlen + t)*KEXT + hu;
                g_Aext[abase]      = hi;
                g_Aext[abase+Dd]   = hi;
                g_Aext[abase+2*Dd] = lo;
            }
        }
        asm volatile("barrier.cluster.wait;" ::: "memory");
        cur = nxt;
    }
}

// ---------------- LayerNorm + fp16 cast for head ----------------
__global__ void ln_kernel(const float* __restrict__ gamma,
                          const float* __restrict__ beta,
                          float* __restrict__ out){
    const int row = blockIdx.x;
    const int tid = threadIdx.x;
    float v = g_h[(size_t)row*Dd + tid];
    float s = v, s2 = v*v;
    #pragma unroll
    for (int o=16;o;o>>=1){
        s  += __shfl_down_sync(0xffffffffu, s,  o);
        s2 += __shfl_down_sync(0xffffffffu, s2, o);
    }
    __shared__ float ws[6], ws2[6];
    __shared__ float mean_s, inv_s;
    int w = tid >> 5, lane = tid & 31;
    if (!lane){ ws[w]=s; ws2[w]=s2; }
    __syncthreads();
    if (tid==0){
        float S=0.f, S2=0.f;
        #pragma unroll
        for (int i=0;i<6;i++){ S+=ws[i]; S2+=ws2[i]; }
        float mu = S * (1.f/Dd);
        float var = S2 * (1.f/Dd) - mu*mu;
        mean_s = mu;
        inv_s  = rsqrtf(var + 1e-5f);
    }
    __syncthreads();
    float y = (v - mean_s) * inv_s * gamma[tid] + beta[tid];
    out[(size_t)row*Dd + tid] = y;
    g_Ahead[(size_t)row*KHEAD + tid] = __float2half_rn(y);
}

// ---------------- launch ----------------
extern "C" void kernel_launch(void* const* d_in, const int* in_sizes, int n_in,
                              void* d_out, int out_size)
{
    const int*   x     = (const int*)  d_in[0];
    const float* tok   = (const float*)d_in[1];
    const float* pos   = (const float*)d_in[2];
    const float* W_ih  = (const float*)d_in[3];
    const float* W_hh  = (const float*)d_in[4];
    const float* b_ih  = (const float*)d_in[5];
    const float* b_hh  = (const float*)d_in[6];
    const float* gamma = (const float*)d_in[7];
    const float* beta  = (const float*)d_in[8];

    float* out_logits = (float*)d_out;
    float* out_h      = (float*)d_out + BTV;

    float *pgx=nullptr;
    __nv_bfloat16 *pAe=nullptr, *pWe=nullptr;
    __half *pAh=nullptr, *pBh=nullptr;
    cudaGetSymbolAddress((void**)&pgx, g_gx);
    cudaGetSymbolAddress((void**)&pAe, g_Aext);
    cudaGetSymbolAddress((void**)&pWe, g_Wext);
    cudaGetSymbolAddress((void**)&pAh, g_Ahead);
    cudaGetSymbolAddress((void**)&pBh, g_Bh);

    cudaFuncSetAttribute((const void*)mma_gemm<9,true>,
        cudaFuncAttributeMaxDynamicSharedMemorySize, GX_SMEM);
    cudaFuncSetAttribute((const void*)head_gemm,
        cudaFuncAttributeMaxDynamicSharedMemorySize, HEAD_SMEM);

    embed_split<<<BT, Dd>>>(x, tok, pos);
    conv_all<<<Vv + Ll*H4d, Dd>>>(tok, W_ih);

    for (int l = 0; l < Ll; l++){
        mma_gemm<9,true><<<dim3(H4d/128, BT/64), 128, GX_SMEM>>>(
            pAe, pWe + (size_t)l*H4d*KEXT,
            b_ih + (size_t)l*H4d, b_hh + (size_t)l*H4d,
            pgx, H4d);
        if (l < Ll-1)
            lstm_kernel<false><<<dim3(4, Bsz), 384>>>(W_hh + (size_t)l*H4d*Dd);
        else
            lstm_kernel<true><<<dim3(4, Bsz), 384>>>(W_hh + (size_t)l*H4d*Dd);
    }

    ln_kernel<<<BT, Dd>>>(gamma, beta, out_h);

    head_gemm<<<dim3(Vv/128, BT/128), 128, HEAD_SMEM>>>(
        pAh, pBh, out_logits, Vv);
}